// round 5
// baseline (speedup 1.0000x reference)
#include <cuda_runtime.h>

#define NSC 16
#define NVC 4
#define EF  48
#define IRR 56
#define WN  832
#define NE  160000
#define NN  8000
#define NTILES (NE / 32)
#define TPB 256

#define INV_SQRT3f 0.57735026918962576451f
#define INV_SQRT2f 0.70710678118654752440f
#define A_SCALf    0.22360679774997896964f   /* 1/sqrt(20) */
#define A_VECf     0.20412414523193150818f   /* 1/sqrt(24) */

__device__ float g_cnt[NN];

// w[j] = b2[j] + sum_k h[k] * W2[k][j], reading the transposed smem copy
// W2T[j][k] via broadcast LDS.128. Two accumulator chains for ILP.
__device__ __forceinline__ float wcomp(const float* __restrict__ sW2T,
                                       const float* __restrict__ sB2,
                                       const float h[EF], int j) {
    const float4* row = reinterpret_cast<const float4*>(sW2T + j * EF);
    float wa = sB2[j];
    float wb = 0.f;
#pragma unroll
    for (int kc = 0; kc < 12; kc += 2) {
        float4 a = row[kc];
        wa = fmaf(h[4*kc+0], a.x, wa);
        wa = fmaf(h[4*kc+1], a.y, wa);
        wa = fmaf(h[4*kc+2], a.z, wa);
        wa = fmaf(h[4*kc+3], a.w, wa);
        float4 b = row[kc+1];
        wb = fmaf(h[4*kc+4], b.x, wb);
        wb = fmaf(h[4*kc+5], b.y, wb);
        wb = fmaf(h[4*kc+6], b.z, wb);
        wb = fmaf(h[4*kc+7], b.w, wb);
    }
    return wa + wb;
}

__global__ __launch_bounds__(TPB, 1)
void tp_main(const float* __restrict__ node_attr,
             const float* __restrict__ edge_attr,
             const float* __restrict__ edge_sh,
             const float* __restrict__ fc_w1,
             const float* __restrict__ fc_b1,
             const float* __restrict__ fc_w2,
             const float* __restrict__ fc_b2,
             const int*   __restrict__ edge_index,
             float*       __restrict__ outp)
{
    extern __shared__ float smem[];
    float* sW2T = smem;                      // [832][48]
    float* sW1T = smem + WN * EF;            // [48][48]
    float* sB1  = sW1T + EF * EF;            // [48]
    float* sB2  = sB1 + EF;                  // [832]

    // Cooperative transpose loads (gmem reads coalesced).
    for (int idx = threadIdx.x; idx < EF * WN; idx += TPB) {
        int k = idx / WN, j = idx - k * WN;
        sW2T[j * EF + k] = fc_w2[idx];
    }
    for (int idx = threadIdx.x; idx < EF * EF; idx += TPB) {
        int k = idx / EF, j = idx - k * EF;
        sW1T[j * EF + k] = fc_w1[idx];
    }
    for (int idx = threadIdx.x; idx < EF; idx += TPB) sB1[idx] = fc_b1[idx];
    for (int idx = threadIdx.x; idx < WN; idx += TPB) sB2[idx] = fc_b2[idx];
    __syncthreads();

    const int lane = threadIdx.x & 31;
    const int wid  = threadIdx.x >> 5;
    const int gw   = blockIdx.x * (TPB / 32) + wid;
    const int nw   = gridDim.x * (TPB / 32);

    for (int tile = gw; tile < NTILES; tile += nw) {
        const int e    = tile * 32 + lane;     // NE is an exact multiple of 32
        const int srcn = edge_index[e];
        const int dstn = edge_index[NE + e];

        // ---------- MLP layer 1: h = relu(ea @ W1 + b1) ----------
        float h[EF];
#pragma unroll
        for (int j = 0; j < EF; j++) h[j] = sB1[j];
        const float4* ea4 = reinterpret_cast<const float4*>(edge_attr) + (size_t)e * 12;
        float4 nxt = __ldg(&ea4[0]);
#pragma unroll 1
        for (int kc = 0; kc < 12; kc++) {
            float4 ea = nxt;
            if (kc < 11) nxt = __ldg(&ea4[kc + 1]);
#pragma unroll
            for (int j = 0; j < EF; j++) {
                float4 ww = *reinterpret_cast<const float4*>(sW1T + j * EF + kc * 4);
                h[j] = fmaf(ea.x, ww.x, h[j]);
                h[j] = fmaf(ea.y, ww.y, h[j]);
                h[j] = fmaf(ea.z, ww.z, h[j]);
                h[j] = fmaf(ea.w, ww.w, h[j]);
            }
        }
#pragma unroll
        for (int j = 0; j < EF; j++) h[j] = fmaxf(h[j], 0.f);

        // ---------- gather node_attr[dst], edge_sh ----------
        float X[IRR];
        {
            const float4* xr = reinterpret_cast<const float4*>(node_attr + (size_t)dstn * IRR);
#pragma unroll
            for (int i = 0; i < 14; i++) {
                float4 v = __ldg(&xr[i]);
                X[4*i+0] = v.x; X[4*i+1] = v.y; X[4*i+2] = v.z; X[4*i+3] = v.w;
            }
        }
        float4 sh = __ldg(reinterpret_cast<const float4*>(edge_sh) + e);
        const float s0 = sh.x, s1x = sh.y, s1y = sh.z, s1z = sh.w;

        // dots and crosses
        float dotb[4], dotc[4], cre[4][3], cro[4][3];
#pragma unroll
        for (int u = 0; u < 4; u++) {
            float ax = X[16+u*3+0], ay = X[16+u*3+1], az = X[16+u*3+2];   // x1o
            dotb[u]  = (ax*s1x + ay*s1y + az*s1z) * INV_SQRT3f;
            cro[u][0] = (ay*s1z - az*s1y) * INV_SQRT2f;
            cro[u][1] = (az*s1x - ax*s1z) * INV_SQRT2f;
            cro[u][2] = (ax*s1y - ay*s1x) * INV_SQRT2f;
            float bx = X[28+u*3+0], by = X[28+u*3+1], bz = X[28+u*3+2];   // x1e
            dotc[u]  = (bx*s1x + by*s1y + bz*s1z) * INV_SQRT3f;
            cre[u][0] = (by*s1z - bz*s1y) * INV_SQRT2f;
            cre[u][1] = (bz*s1x - bx*s1z) * INV_SQRT2f;
            cre[u][2] = (bx*s1y - by*s1x) * INV_SQRT2f;
        }

        float* ob = outp + (size_t)srcn * IRR;

        // ---------- o0e : paths wA0 (off 0) + wB0 (off 256) ----------
#pragma unroll 1
        for (int v = 0; v < 16; v++) {
            float aA = 0.f;
#pragma unroll
            for (int u = 0; u < 16; u++)
                aA = fmaf(X[u], wcomp(sW2T, sB2, h, 0 + u*16 + v), aA);
            float aB = 0.f;
#pragma unroll
            for (int u = 0; u < 4; u++)
                aB = fmaf(dotb[u], wcomp(sW2T, sB2, h, 256 + u*16 + v), aB);
            atomicAdd(ob + v, fmaf(aA, s0, aB) * A_SCALf);
        }

        // ---------- o1o : wA1 (320) + wB1 (384) + wC1 (400) ----------
#pragma unroll 1
        for (int v = 0; v < 4; v++) {
            float t = 0.f;
#pragma unroll
            for (int u = 0; u < 16; u++)
                t = fmaf(X[u], wcomp(sW2T, sB2, h, 320 + u*4 + v), t);
            float b0 = 0.f, b1 = 0.f, b2 = 0.f;
#pragma unroll
            for (int u = 0; u < 4; u++) {
                float w = wcomp(sW2T, sB2, h, 384 + u*4 + v);
                b0 = fmaf(X[16+u*3+0], w, b0);
                b1 = fmaf(X[16+u*3+1], w, b1);
                b2 = fmaf(X[16+u*3+2], w, b2);
            }
            float c0 = 0.f, c1 = 0.f, c2 = 0.f;
#pragma unroll
            for (int u = 0; u < 4; u++) {
                float w = wcomp(sW2T, sB2, h, 400 + u*4 + v);
                c0 = fmaf(cre[u][0], w, c0);
                c1 = fmaf(cre[u][1], w, c1);
                c2 = fmaf(cre[u][2], w, c2);
            }
            atomicAdd(ob + 16 + v*3 + 0, fmaf(t, s1x, fmaf(b0, s0, c0)) * A_VECf);
            atomicAdd(ob + 16 + v*3 + 1, fmaf(t, s1y, fmaf(b1, s0, c1)) * A_VECf);
            atomicAdd(ob + 16 + v*3 + 2, fmaf(t, s1z, fmaf(b2, s0, c2)) * A_VECf);
        }

        // ---------- o1e : wB1e (416) + wC1e (432) + wD1e (448) ----------
#pragma unroll 1
        for (int v = 0; v < 4; v++) {
            float p0 = 0.f, p1 = 0.f, p2 = 0.f;
#pragma unroll
            for (int u = 0; u < 4; u++) {
                float w = wcomp(sW2T, sB2, h, 416 + u*4 + v);
                p0 = fmaf(cro[u][0], w, p0);
                p1 = fmaf(cro[u][1], w, p1);
                p2 = fmaf(cro[u][2], w, p2);
            }
            float q0 = 0.f, q1 = 0.f, q2 = 0.f;
#pragma unroll
            for (int u = 0; u < 4; u++) {
                float w = wcomp(sW2T, sB2, h, 432 + u*4 + v);
                q0 = fmaf(X[28+u*3+0], w, q0);
                q1 = fmaf(X[28+u*3+1], w, q1);
                q2 = fmaf(X[28+u*3+2], w, q2);
            }
            float t2 = 0.f;
#pragma unroll
            for (int u = 0; u < 16; u++)
                t2 = fmaf(X[40+u], wcomp(sW2T, sB2, h, 448 + u*4 + v), t2);
            atomicAdd(ob + 28 + v*3 + 0, fmaf(t2, s1x, fmaf(q0, s0, p0)) * A_VECf);
            atomicAdd(ob + 28 + v*3 + 1, fmaf(t2, s1y, fmaf(q1, s0, p1)) * A_VECf);
            atomicAdd(ob + 28 + v*3 + 2, fmaf(t2, s1z, fmaf(q2, s0, p2)) * A_VECf);
        }

        // ---------- o0o : wC0o (512) + wD0o (576) ----------
#pragma unroll 1
        for (int v = 0; v < 16; v++) {
            float aC = 0.f;
#pragma unroll
            for (int u = 0; u < 4; u++)
                aC = fmaf(dotc[u], wcomp(sW2T, sB2, h, 512 + u*16 + v), aC);
            float aD = 0.f;
#pragma unroll
            for (int u = 0; u < 16; u++)
                aD = fmaf(X[40+u], wcomp(sW2T, sB2, h, 576 + u*16 + v), aD);
            atomicAdd(ob + 40 + v, fmaf(aD, s0, aC) * A_SCALf);
        }

        atomicAdd(&g_cnt[srcn], 1.0f);
    }
}

__global__ void zero_kernel(float* __restrict__ outp) {
    int i = blockIdx.x * blockDim.x + threadIdx.x;
    if (i < NN * IRR) outp[i] = 0.f;
    if (i < NN) g_cnt[i] = 0.f;
}

__global__ void div_kernel(float* __restrict__ outp) {
    int i = blockIdx.x * blockDim.x + threadIdx.x;
    if (i < NN * IRR) {
        float c = g_cnt[i / IRR];
        outp[i] = outp[i] / fmaxf(c, 1.0f);
    }
}

extern "C" void kernel_launch(void* const* d_in, const int* in_sizes, int n_in,
                              void* d_out, int out_size) {
    const float* node_attr  = (const float*)d_in[0];
    const float* edge_attr  = (const float*)d_in[1];
    const float* edge_sh    = (const float*)d_in[2];
    const float* fc_w1      = (const float*)d_in[3];
    const float* fc_b1      = (const float*)d_in[4];
    const float* fc_w2      = (const float*)d_in[5];
    const float* fc_b2      = (const float*)d_in[6];
    const int*   edge_index = (const int*)d_in[7];
    float* outp = (float*)d_out;

    const int smem_bytes = (WN * EF + EF * EF + EF + WN) * (int)sizeof(float); // 172480
    cudaFuncSetAttribute(tp_main, cudaFuncAttributeMaxDynamicSharedMemorySize, smem_bytes);

    int nsm = 148;
    cudaDeviceGetAttribute(&nsm, cudaDevAttrMultiProcessorCount, 0);

    const int nz = (NN * IRR + 255) / 256;
    zero_kernel<<<nz, 256>>>(outp);
    tp_main<<<nsm, TPB, smem_bytes>>>(node_attr, edge_attr, edge_sh,
                                      fc_w1, fc_b1, fc_w2, fc_b2,
                                      edge_index, outp);
    div_kernel<<<nz, 256>>>(outp);
}

// round 8
// speedup vs baseline: 1.0404x; 1.0404x over previous
#include <cuda_runtime.h>

#define NSC 16
#define NVC 4
#define EF  48
#define IRR 56
#define WN  832
#define NE  160000
#define NN  8000
#define NTILES (NE / 32)
#define TPB 256

#define INV_SQRT3f 0.57735026918962576451f
#define INV_SQRT2f 0.70710678118654752440f
#define A_SCALf    0.22360679774997896964f   /* 1/sqrt(20) */
#define A_VECf     0.20412414523193150818f   /* 1/sqrt(24) */

typedef unsigned long long u64;

__device__ float g_cnt[NN];

// ---- f32x2 packed helpers (sm_103a FFMA2 path; ptxas never emits these) ----
__device__ __forceinline__ u64 bcast2(float v) {
    u64 r; unsigned x = __float_as_uint(v);
    asm("mov.b64 %0, {%1, %2};" : "=l"(r) : "r"(x), "r"(x));
    return r;
}
__device__ __forceinline__ void ffma2(u64 &d, u64 a, u64 b) {
    asm("fma.rn.f32x2 %0, %1, %2, %3;" : "=l"(d) : "l"(a), "l"(b), "l"(d));
}
__device__ __forceinline__ u64 fadd2(u64 a, u64 b) {
    u64 r; asm("add.rn.f32x2 %0, %1, %2;" : "=l"(r) : "l"(a), "l"(b));
    return r;
}
__device__ __forceinline__ float hsum2(u64 v) {
    unsigned lo, hi;
    asm("mov.b64 {%0, %1}, %2;" : "=r"(lo), "=r"(hi) : "l"(v));
    return __uint_as_float(lo) + __uint_as_float(hi);
}

// w[j] = b2[j] + sum_k h[k]*W2[k][j] via transposed smem row and packed FFMA2.
// h2[i] packs (h[2i], h[2i+1]); row delivers matching weight pairs via LDS.128.
__device__ __forceinline__ float wcomp(const float* __restrict__ sW2T,
                                       const float* __restrict__ sB2,
                                       const u64 h2[24], int j) {
    const ulonglong2* row = reinterpret_cast<const ulonglong2*>(sW2T + j * EF);
    u64 a0 = 0ull, a1 = 0ull;
#pragma unroll
    for (int kc = 0; kc < 12; kc += 2) {
        ulonglong2 r0 = row[kc];
        ffma2(a0, h2[2*kc+0], r0.x);
        ffma2(a1, h2[2*kc+1], r0.y);
        ulonglong2 r1 = row[kc+1];
        ffma2(a0, h2[2*kc+2], r1.x);
        ffma2(a1, h2[2*kc+3], r1.y);
    }
    return sB2[j] + hsum2(fadd2(a0, a1));
}

__global__ __launch_bounds__(TPB, 1)
void tp_main(const float* __restrict__ node_attr,
             const float* __restrict__ edge_attr,
             const float* __restrict__ edge_sh,
             const float* __restrict__ fc_w1,
             const float* __restrict__ fc_b1,
             const float* __restrict__ fc_w2,
             const float* __restrict__ fc_b2,
             const int*   __restrict__ edge_index,
             float*       __restrict__ outp)
{
    extern __shared__ float smem[];
    float* sW2T = smem;                      // [832][48]  (transposed: row j, k contiguous)
    float* sW1  = smem + WN * EF;            // [48][48]   (direct: row k, j contiguous)
    float* sB1  = sW1 + EF * EF;             // [48]  (16B aligned)
    float* sB2  = sB1 + EF;                  // [832]

    // W2 transposed cooperatively (gmem reads coalesced over j).
    for (int idx = threadIdx.x; idx < EF * WN; idx += TPB) {
        int k = idx / WN, j = idx - k * WN;
        sW2T[j * EF + k] = fc_w2[idx];
    }
    // W1 copied directly — layer 1 runs j-packed against original layout.
    for (int idx = threadIdx.x; idx < EF * EF; idx += TPB) sW1[idx] = fc_w1[idx];
    for (int idx = threadIdx.x; idx < EF; idx += TPB) sB1[idx] = fc_b1[idx];
    for (int idx = threadIdx.x; idx < WN; idx += TPB) sB2[idx] = fc_b2[idx];
    __syncthreads();

    const int lane = threadIdx.x & 31;
    const int wid  = threadIdx.x >> 5;
    const int gw   = blockIdx.x * (TPB / 32) + wid;
    const int nw   = gridDim.x * (TPB / 32);

    for (int tile = gw; tile < NTILES; tile += nw) {
        const int e    = tile * 32 + lane;     // NE is an exact multiple of 32
        const int srcn = edge_index[e];
        const int dstn = edge_index[NE + e];

        // ---------- MLP layer 1 (j-packed FFMA2): h2[i] = relu pair (h[2i],h[2i+1]) ----------
        u64 h2[24];
        {
            const u64* b1p = reinterpret_cast<const u64*>(sB1);
#pragma unroll
            for (int i = 0; i < 24; i++) h2[i] = b1p[i];

            const float4* ea4 = reinterpret_cast<const float4*>(edge_attr) + (size_t)e * 12;
            float4 nxt = __ldg(&ea4[0]);
#pragma unroll 1
            for (int kc = 0; kc < 12; kc++) {
                float4 ea = nxt;
                if (kc < 11) nxt = __ldg(&ea4[kc + 1]);
                u64 e0 = bcast2(ea.x), e1 = bcast2(ea.y);
                u64 e2 = bcast2(ea.z), e3 = bcast2(ea.w);
                const ulonglong2* r0 = reinterpret_cast<const ulonglong2*>(sW1 + (kc*4+0)*EF);
                const ulonglong2* r1 = reinterpret_cast<const ulonglong2*>(sW1 + (kc*4+1)*EF);
                const ulonglong2* r2 = reinterpret_cast<const ulonglong2*>(sW1 + (kc*4+2)*EF);
                const ulonglong2* r3 = reinterpret_cast<const ulonglong2*>(sW1 + (kc*4+3)*EF);
#pragma unroll
                for (int jj = 0; jj < 12; jj++) {
                    ulonglong2 w0 = r0[jj];
                    ffma2(h2[2*jj], e0, w0.x); ffma2(h2[2*jj+1], e0, w0.y);
                    ulonglong2 w1 = r1[jj];
                    ffma2(h2[2*jj], e1, w1.x); ffma2(h2[2*jj+1], e1, w1.y);
                    ulonglong2 w2 = r2[jj];
                    ffma2(h2[2*jj], e2, w2.x); ffma2(h2[2*jj+1], e2, w2.y);
                    ulonglong2 w3 = r3[jj];
                    ffma2(h2[2*jj], e3, w3.x); ffma2(h2[2*jj+1], e3, w3.y);
                }
            }
            // ReLU on packed pairs
#pragma unroll
            for (int i = 0; i < 24; i++) {
                unsigned lo, hi;
                asm("mov.b64 {%0, %1}, %2;" : "=r"(lo), "=r"(hi) : "l"(h2[i]));
                float flo = fmaxf(__uint_as_float(lo), 0.f);
                float fhi = fmaxf(__uint_as_float(hi), 0.f);
                asm("mov.b64 %0, {%1, %2};" : "=l"(h2[i])
                    : "r"(__float_as_uint(flo)), "r"(__float_as_uint(fhi)));
            }
        }

        // ---------- gather node_attr[dst], edge_sh ----------
        float X[IRR];
        {
            const float4* xr = reinterpret_cast<const float4*>(node_attr + (size_t)dstn * IRR);
#pragma unroll
            for (int i = 0; i < 14; i++) {
                float4 v = __ldg(&xr[i]);
                X[4*i+0] = v.x; X[4*i+1] = v.y; X[4*i+2] = v.z; X[4*i+3] = v.w;
            }
        }
        float4 sh = __ldg(reinterpret_cast<const float4*>(edge_sh) + e);
        const float s0 = sh.x, s1x = sh.y, s1y = sh.z, s1z = sh.w;

        // dots and crosses
        float dotb[4], dotc[4], cre[4][3], cro[4][3];
#pragma unroll
        for (int u = 0; u < 4; u++) {
            float ax = X[16+u*3+0], ay = X[16+u*3+1], az = X[16+u*3+2];   // x1o
            dotb[u]  = (ax*s1x + ay*s1y + az*s1z) * INV_SQRT3f;
            cro[u][0] = (ay*s1z - az*s1y) * INV_SQRT2f;
            cro[u][1] = (az*s1x - ax*s1z) * INV_SQRT2f;
            cro[u][2] = (ax*s1y - ay*s1x) * INV_SQRT2f;
            float bx = X[28+u*3+0], by = X[28+u*3+1], bz = X[28+u*3+2];   // x1e
            dotc[u]  = (bx*s1x + by*s1y + bz*s1z) * INV_SQRT3f;
            cre[u][0] = (by*s1z - bz*s1y) * INV_SQRT2f;
            cre[u][1] = (bz*s1x - bx*s1z) * INV_SQRT2f;
            cre[u][2] = (bx*s1y - by*s1x) * INV_SQRT2f;
        }

        float* ob = outp + (size_t)srcn * IRR;

        // ---------- o0e : paths wA0 (off 0) + wB0 (off 256) ----------
#pragma unroll 1
        for (int v = 0; v < 16; v++) {
            float aA = 0.f;
#pragma unroll
            for (int u = 0; u < 16; u++)
                aA = fmaf(X[u], wcomp(sW2T, sB2, h2, 0 + u*16 + v), aA);
            float aB = 0.f;
#pragma unroll
            for (int u = 0; u < 4; u++)
                aB = fmaf(dotb[u], wcomp(sW2T, sB2, h2, 256 + u*16 + v), aB);
            atomicAdd(ob + v, fmaf(aA, s0, aB) * A_SCALf);
        }

        // ---------- o1o : wA1 (320) + wB1 (384) + wC1 (400) ----------
#pragma unroll 1
        for (int v = 0; v < 4; v++) {
            float t = 0.f;
#pragma unroll
            for (int u = 0; u < 16; u++)
                t = fmaf(X[u], wcomp(sW2T, sB2, h2, 320 + u*4 + v), t);
            float b0 = 0.f, b1 = 0.f, b2 = 0.f;
#pragma unroll
            for (int u = 0; u < 4; u++) {
                float w = wcomp(sW2T, sB2, h2, 384 + u*4 + v);
                b0 = fmaf(X[16+u*3+0], w, b0);
                b1 = fmaf(X[16+u*3+1], w, b1);
                b2 = fmaf(X[16+u*3+2], w, b2);
            }
            float c0 = 0.f, c1 = 0.f, c2 = 0.f;
#pragma unroll
            for (int u = 0; u < 4; u++) {
                float w = wcomp(sW2T, sB2, h2, 400 + u*4 + v);
                c0 = fmaf(cre[u][0], w, c0);
                c1 = fmaf(cre[u][1], w, c1);
                c2 = fmaf(cre[u][2], w, c2);
            }
            atomicAdd(ob + 16 + v*3 + 0, fmaf(t, s1x, fmaf(b0, s0, c0)) * A_VECf);
            atomicAdd(ob + 16 + v*3 + 1, fmaf(t, s1y, fmaf(b1, s0, c1)) * A_VECf);
            atomicAdd(ob + 16 + v*3 + 2, fmaf(t, s1z, fmaf(b2, s0, c2)) * A_VECf);
        }

        // ---------- o1e : wB1e (416) + wC1e (432) + wD1e (448) ----------
#pragma unroll 1
        for (int v = 0; v < 4; v++) {
            float p0 = 0.f, p1 = 0.f, p2 = 0.f;
#pragma unroll
            for (int u = 0; u < 4; u++) {
                float w = wcomp(sW2T, sB2, h2, 416 + u*4 + v);
                p0 = fmaf(cro[u][0], w, p0);
                p1 = fmaf(cro[u][1], w, p1);
                p2 = fmaf(cro[u][2], w, p2);
            }
            float q0 = 0.f, q1 = 0.f, q2 = 0.f;
#pragma unroll
            for (int u = 0; u < 4; u++) {
                float w = wcomp(sW2T, sB2, h2, 432 + u*4 + v);
                q0 = fmaf(X[28+u*3+0], w, q0);
                q1 = fmaf(X[28+u*3+1], w, q1);
                q2 = fmaf(X[28+u*3+2], w, q2);
            }
            float t2 = 0.f;
#pragma unroll
            for (int u = 0; u < 16; u++)
                t2 = fmaf(X[40+u], wcomp(sW2T, sB2, h2, 448 + u*4 + v), t2);
            atomicAdd(ob + 28 + v*3 + 0, fmaf(t2, s1x, fmaf(q0, s0, p0)) * A_VECf);
            atomicAdd(ob + 28 + v*3 + 1, fmaf(t2, s1y, fmaf(q1, s0, p1)) * A_VECf);
            atomicAdd(ob + 28 + v*3 + 2, fmaf(t2, s1z, fmaf(q2, s0, p2)) * A_VECf);
        }

        // ---------- o0o : wC0o (512) + wD0o (576) ----------
#pragma unroll 1
        for (int v = 0; v < 16; v++) {
            float aC = 0.f;
#pragma unroll
            for (int u = 0; u < 4; u++)
                aC = fmaf(dotc[u], wcomp(sW2T, sB2, h2, 512 + u*16 + v), aC);
            float aD = 0.f;
#pragma unroll
            for (int u = 0; u < 16; u++)
                aD = fmaf(X[40+u], wcomp(sW2T, sB2, h2, 576 + u*16 + v), aD);
            atomicAdd(ob + 40 + v, fmaf(aD, s0, aC) * A_SCALf);
        }

        atomicAdd(&g_cnt[srcn], 1.0f);
    }
}

__global__ void zero_kernel(float* __restrict__ outp) {
    int i = blockIdx.x * blockDim.x + threadIdx.x;
    if (i < NN * IRR) outp[i] = 0.f;
    if (i < NN) g_cnt[i] = 0.f;
}

__global__ void div_kernel(float* __restrict__ outp) {
    int i = blockIdx.x * blockDim.x + threadIdx.x;
    if (i < NN * IRR) {
        float c = g_cnt[i / IRR];
        outp[i] = outp[i] / fmaxf(c, 1.0f);
    }
}

extern "C" void kernel_launch(void* const* d_in, const int* in_sizes, int n_in,
                              void* d_out, int out_size) {
    const float* node_attr  = (const float*)d_in[0];
    const float* edge_attr  = (const float*)d_in[1];
    const float* edge_sh    = (const float*)d_in[2];
    const float* fc_w1      = (const float*)d_in[3];
    const float* fc_b1      = (const float*)d_in[4];
    const float* fc_w2      = (const float*)d_in[5];
    const float* fc_b2      = (const float*)d_in[6];
    const int*   edge_index = (const int*)d_in[7];
    float* outp = (float*)d_out;

    const int smem_bytes = (WN * EF + EF * EF + EF + WN) * (int)sizeof(float); // 172480
    cudaFuncSetAttribute(tp_main, cudaFuncAttributeMaxDynamicSharedMemorySize, smem_bytes);

    int nsm = 148;
    cudaDeviceGetAttribute(&nsm, cudaDevAttrMultiProcessorCount, 0);

    const int nz = (NN * IRR + 255) / 256;
    zero_kernel<<<nz, 256>>>(outp);
    tp_main<<<nsm, TPB, smem_bytes>>>(node_attr, edge_attr, edge_sh,
                                      fc_w1, fc_b1, fc_w2, fc_b2,
                                      edge_index, outp);
    div_kernel<<<nz, 256>>>(outp);
}